// round 14
// baseline (speedup 1.0000x reference)
#include <cuda_runtime.h>
#include <cuda_fp16.h>
#include <math.h>

#define BATCH  2
#define SEQ    2048
#define DMODEL 256
#define NHEAD  8
#define DH     32
#define MTOT   (BATCH*SEQ)   // 4096
// Wq pre-scale: 1/sqrt(32) * log2(e), so S arrives in the log2 domain
#define WQ_SCALE (0.17677669529663687f * 1.4426950408889634f)

// attention dynamic smem: Q[128][40] + K[2][2][128][40] + V[2][2][128][40]
#define ATTN_SMEM_HALVES (128*40 + 2*2*128*40 + 2*2*128*40)
#define ATTN_SMEM_BYTES  (ATTN_SMEM_HALVES * 2)   // 92160 B

// scratch (no cudaMalloc allowed)
__device__ __half g_q  [MTOT*DMODEL];   // projected q (WQ_SCALE folded)
__device__ __half g_k  [MTOT*DMODEL];
__device__ __half g_v  [MTOT*DMODEL];
__device__ __half g_aoh[MTOT*DMODEL];   // attention output (half)

__device__ __forceinline__ unsigned int smem_addr_u32(const void* generic_ptr) {
    return (unsigned int)__cvta_generic_to_shared(generic_ptr);
}
__device__ __forceinline__ void cp_async16(unsigned int dst_smem, const void* src_gmem) {
    asm volatile("cp.async.cg.shared.global [%0], [%1], 16;" :: "r"(dst_smem), "l"(src_gmem));
}
__device__ __forceinline__ void cp_async_commit() {
    asm volatile("cp.async.commit_group;" ::: "memory");
}
__device__ __forceinline__ void cp_async_wait_one() {
    asm volatile("cp.async.wait_group 1;" ::: "memory");
}
__device__ __forceinline__ void ldmatrix_x4(unsigned int& mr0, unsigned int& mr1,
                                            unsigned int& mr2, unsigned int& mr3,
                                            unsigned int src_smem) {
    asm volatile("ldmatrix.sync.aligned.m8n8.x4.shared.b16 {%0,%1,%2,%3}, [%4];"
                 : "=r"(mr0), "=r"(mr1), "=r"(mr2), "=r"(mr3) : "r"(src_smem));
}
__device__ __forceinline__ void ldmatrix_x4_trans(unsigned int& mr0, unsigned int& mr1,
                                                  unsigned int& mr2, unsigned int& mr3,
                                                  unsigned int src_smem) {
    asm volatile("ldmatrix.sync.aligned.m8n8.x4.trans.shared.b16 {%0,%1,%2,%3}, [%4];"
                 : "=r"(mr0), "=r"(mr1), "=r"(mr2), "=r"(mr3) : "r"(src_smem));
}
__device__ __forceinline__ void mma_f16_16816(float& acc0, float& acc1, float& acc2, float& acc3,
                                              unsigned int fa0, unsigned int fa1,
                                              unsigned int fa2, unsigned int fa3,
                                              unsigned int fb0, unsigned int fb1) {
    asm volatile("mma.sync.aligned.m16n8k16.row.col.f32.f16.f16.f32 "
                 "{%0,%1,%2,%3}, {%4,%5,%6,%7}, {%8,%9}, {%0,%1,%2,%3};"
                 : "+f"(acc0), "+f"(acc1), "+f"(acc2), "+f"(acc3)
                 : "r"(fa0), "r"(fa1), "r"(fa2), "r"(fa3), "r"(fb0), "r"(fb1));
}
__device__ __forceinline__ unsigned int pack_f16x2(float lo_val, float hi_val) {
    unsigned int packed_result;
    asm("cvt.rn.f16x2.f32 %0, %1, %2;" : "=r"(packed_result) : "f"(hi_val), "f"(lo_val));
    return packed_result;
}
__device__ __forceinline__ unsigned int exp2_f16x2(unsigned int packed_in) {
    unsigned int packed_out;
    asm("ex2.approx.f16x2 %0, %1;" : "=r"(packed_out) : "r"(packed_in));
    return packed_out;
}
__device__ __forceinline__ void unpack_f16x2(float& out_lo, float& out_hi, unsigned int packed_in) {
    asm("{ .reg .f16 plo, phi;\n\t"
        "  mov.b32 {plo, phi}, %2;\n\t"
        "  cvt.f32.f16 %0, plo;\n\t"
        "  cvt.f32.f16 %1, phi; }"
        : "=f"(out_lo), "=f"(out_hi) : "r"(packed_in));
}

// ---------------------------------------------------------------------------
// QKV projection, fp32 inputs fused: out[m,n] = sum_k X[m,k] * W[n,k].
// fp32 tiles staged via cp.async (double-buffered), converted LDS->cvt->STS
// into a single fp16 staging tile, then the proven ldmatrix/mma path.
// Prefetch targets only the fp32 staging buffers, which the convert pass has
// fully consumed before the barrier preceding the prefetch -- no read race.
// ---------------------------------------------------------------------------
__global__ void __launch_bounds__(256)
proj_gemm_f32in(const float* __restrict__ q_in, const float* __restrict__ k_in,
                const float* __restrict__ v_in, const float* __restrict__ Wq,
                const float* __restrict__ Wk, const float* __restrict__ Wv)
{
    __shared__ __align__(16) float  stage_x32[2][64][36];
    __shared__ __align__(16) float  stage_w32[2][64][36];
    __shared__ __align__(16) __half tile_xh[64][40];
    __shared__ __align__(16) __half tile_wh[64][40];

    const int which = blockIdx.z;
    const float* Xf; const float* Wf; __half* Oh; float wscale;
    if (which == 0)      { Xf = q_in; Wf = Wq; Oh = g_q; wscale = WQ_SCALE; }
    else if (which == 1) { Xf = k_in; Wf = Wk; Oh = g_k; wscale = 1.0f; }
    else                 { Xf = v_in; Wf = Wv; Oh = g_v; wscale = 1.0f; }

    const int tid     = threadIdx.x;
    const int warp_id = tid / 32;
    const int ln      = tid % 32;
    const int wrow0   = (warp_id & 3) * 16;
    const int wcol0   = (warp_id >> 2) * 32;
    const int ln_lo7  = ln & 7;
    const int ln_c4   = ln >> 3;
    const int m0      = blockIdx.y * 64;
    const int n0      = blockIdx.x * 64;

    const int crow  = tid >> 2;          // 0..63
    const int ccol8 = (tid & 3) * 8;     // 0,8,16,24

    auto load_stage = [&](int stage, int kc) {
        const float* xsrc = Xf + (size_t)(m0 + crow) * DMODEL + kc * 32;
        const float* wsrc = Wf + (size_t)(n0 + crow) * DMODEL + kc * 32;
        #pragma unroll
        for (int s = 0; s < 2; s++) {
            const int seg = (tid & 3) + s * 4;
            cp_async16(smem_addr_u32(&stage_x32[stage][crow][0]) + seg * 16, xsrc + seg * 4);
            cp_async16(smem_addr_u32(&stage_w32[stage][crow][0]) + seg * 16, wsrc + seg * 4);
        }
        cp_async_commit();
    };

    load_stage(0, 0);
    load_stage(1, 1);

    float acc[4][4] = {};

    for (int kc = 0; kc < 8; kc++) {
        const int buf = kc & 1;
        cp_async_wait_one();
        __syncthreads();   // fp32 buf ready AND previous mma done reading tiles

        // convert fp32 -> fp16 staging
        {
            float4 fx_a = *(const float4*)&stage_x32[buf][crow][ccol8];
            float4 fx_b = *(const float4*)&stage_x32[buf][crow][ccol8 + 4];
            __half2 hx[4];
            hx[0] = __floats2half2_rn(fx_a.x, fx_a.y);
            hx[1] = __floats2half2_rn(fx_a.z, fx_a.w);
            hx[2] = __floats2half2_rn(fx_b.x, fx_b.y);
            hx[3] = __floats2half2_rn(fx_b.z, fx_b.w);
            *(uint4*)&tile_xh[crow][ccol8] = *(uint4*)&hx[0];

            float4 fw_a = *(const float4*)&stage_w32[buf][crow][ccol8];
            float4 fw_b = *(const float4*)&stage_w32[buf][crow][ccol8 + 4];
            __half2 hw[4];
            hw[0] = __floats2half2_rn(fw_a.x * wscale, fw_a.y * wscale);
            hw[1] = __floats2half2_rn(fw_a.z * wscale, fw_a.w * wscale);
            hw[2] = __floats2half2_rn(fw_b.x * wscale, fw_b.y * wscale);
            hw[3] = __floats2half2_rn(fw_b.z * wscale, fw_b.w * wscale);
            *(uint4*)&tile_wh[crow][ccol8] = *(uint4*)&hw[0];
        }
        __syncthreads();   // staging ready; fp32 buf fully consumed

        // prefetch kc+2 into the now-free fp32 buf (NOT into the fp16 tiles)
        if (kc + 2 < 8) load_stage(buf, kc + 2);
        else            cp_async_commit();   // keep group count invariant

        // mma on the fp16 staging tiles (K=32 chunk)
        unsigned int fa[2][4];
        #pragma unroll
        for (int ks = 0; ks < 2; ks++) {
            ldmatrix_x4(fa[ks][0], fa[ks][1], fa[ks][2], fa[ks][3],
                        smem_addr_u32(&tile_xh[wrow0 + (ln & 15)][ks * 16 + ((ln >> 4) & 1) * 8]));
        }
        #pragma unroll
        for (int nn = 0; nn < 4; nn++) {
            unsigned int wb0, wb1, wb2, wb3;
            ldmatrix_x4(wb0, wb1, wb2, wb3,
                        smem_addr_u32(&tile_wh[wcol0 + nn * 8 + ln_lo7][ln_c4 * 8]));
            mma_f16_16816(acc[nn][0], acc[nn][1], acc[nn][2], acc[nn][3],
                          fa[0][0], fa[0][1], fa[0][2], fa[0][3], wb0, wb1);
            mma_f16_16816(acc[nn][0], acc[nn][1], acc[nn][2], acc[nn][3],
                          fa[1][0], fa[1][1], fa[1][2], fa[1][3], wb2, wb3);
        }
    }

    const int out_row = ln >> 2;
    __half* dst = Oh + (size_t)(m0 + wrow0 + out_row) * DMODEL + n0 + wcol0;
    #pragma unroll
    for (int nn = 0; nn < 4; nn++) {
        const int colx = nn * 8 + (ln & 3) * 2;
        *(__half2*)&dst[colx]              = __floats2half2_rn(acc[nn][0], acc[nn][1]);
        *(__half2*)&dst[8 * DMODEL + colx] = __floats2half2_rn(acc[nn][2], acc[nn][3]);
    }
}

// ---------------------------------------------------------------------------
// Output projection: X = g_aoh (fp16, cp.async direct, double-buffered);
// W = Wo (fp32, staged + converted). RACE FIX vs round 13: the X A-fragments
// are loaded from tile_x2[buf] BEFORE the prefetch that overwrites that
// buffer is issued; the prefetch goes after the barrier that closes all
// tile_x2[buf] reads.
// ---------------------------------------------------------------------------
__global__ void __launch_bounds__(256)
out_proj_f32w(const float* __restrict__ Wo, const float* __restrict__ bo,
              float* __restrict__ out)
{
    __shared__ __align__(16) __half tile_x2[2][64][40];
    __shared__ __align__(16) float  stage_w32[2][64][36];
    __shared__ __align__(16) __half tile_wh[64][40];

    const int tid     = threadIdx.x;
    const int warp_id = tid / 32;
    const int ln      = tid % 32;
    const int wrow0   = (warp_id & 3) * 16;
    const int wcol0   = (warp_id >> 2) * 32;
    const int ln_lo7  = ln & 7;
    const int ln_c4   = ln >> 3;
    const int m0      = blockIdx.y * 64;
    const int n0      = blockIdx.x * 64;

    const int crow  = tid >> 2;
    const int ccol8 = (tid & 3) * 8;

    auto load_stage = [&](int stage, int kc) {
        const __half* xsrc = g_aoh + (size_t)(m0 + crow) * DMODEL + kc * 32;
        cp_async16(smem_addr_u32(&tile_x2[stage][crow][0]) + (tid & 3) * 16,
                   xsrc + (tid & 3) * 8);
        const float* wsrc = Wo + (size_t)(n0 + crow) * DMODEL + kc * 32;
        #pragma unroll
        for (int s = 0; s < 2; s++) {
            const int seg = (tid & 3) + s * 4;
            cp_async16(smem_addr_u32(&stage_w32[stage][crow][0]) + seg * 16, wsrc + seg * 4);
        }
        cp_async_commit();
    };

    load_stage(0, 0);
    load_stage(1, 1);

    float acc[4][4] = {};

    for (int kc = 0; kc < 8; kc++) {
        const int buf = kc & 1;
        cp_async_wait_one();
        __syncthreads();   // buf's X and W data landed; previous iter's reads done

        // convert W fp32 -> fp16 staging
        {
            float4 fw_a = *(const float4*)&stage_w32[buf][crow][ccol8];
            float4 fw_b = *(const float4*)&stage_w32[buf][crow][ccol8 + 4];
            __half2 hw[4];
            hw[0] = __floats2half2_rn(fw_a.x, fw_a.y);
            hw[1] = __floats2half2_rn(fw_a.z, fw_a.w);
            hw[2] = __floats2half2_rn(fw_b.x, fw_b.y);
            hw[3] = __floats2half2_rn(fw_b.z, fw_b.w);
            *(uint4*)&tile_wh[crow][ccol8] = *(uint4*)&hw[0];
        }

        // load X A-fragments BEFORE the prefetch can overwrite tile_x2[buf]
        unsigned int fa[2][4];
        #pragma unroll
        for (int ks = 0; ks < 2; ks++) {
            ldmatrix_x4(fa[ks][0], fa[ks][1], fa[ks][2], fa[ks][3],
                        smem_addr_u32(&tile_x2[buf][wrow0 + (ln & 15)][ks * 16 + ((ln >> 4) & 1) * 8]));
        }

        __syncthreads();   // tile_wh written by all; all tile_x2[buf] reads done

        if (kc + 2 < 8) load_stage(buf, kc + 2);   // safe: tile_x2[buf] consumed
        else            cp_async_commit();

        #pragma unroll
        for (int nn = 0; nn < 4; nn++) {
            unsigned int wb0, wb1, wb2, wb3;
            ldmatrix_x4(wb0, wb1, wb2, wb3,
                        smem_addr_u32(&tile_wh[wcol0 + nn * 8 + ln_lo7][ln_c4 * 8]));
            mma_f16_16816(acc[nn][0], acc[nn][1], acc[nn][2], acc[nn][3],
                          fa[0][0], fa[0][1], fa[0][2], fa[0][3], wb0, wb1);
            mma_f16_16816(acc[nn][0], acc[nn][1], acc[nn][2], acc[nn][3],
                          fa[1][0], fa[1][1], fa[1][2], fa[1][3], wb2, wb3);
        }
    }

    const int out_row = ln >> 2;
    float* dst = out + (size_t)(m0 + wrow0 + out_row) * DMODEL + n0 + wcol0;
    #pragma unroll
    for (int nn = 0; nn < 4; nn++) {
        const int colx = nn * 8 + (ln & 3) * 2;
        const float bia0 = bo[n0 + wcol0 + colx];
        const float bia1 = bo[n0 + wcol0 + colx + 1];
        float2 val_lo = { acc[nn][0] + bia0, acc[nn][1] + bia1 };
        float2 val_hi = { acc[nn][2] + bia0, acc[nn][3] + bia1 };
        *(float2*)&dst[colx]              = val_lo;
        *(float2*)&dst[8 * DMODEL + colx] = val_hi;
    }
}

// ---------------------------------------------------------------------------
// Flash attention, fp16 mma.sync, split-K over keys, 128-row K-tiles
// (unchanged from round 12 -- at legacy-HMMA roofline).
// ---------------------------------------------------------------------------
__global__ void __launch_bounds__(512, 2)
attn_flash_splitk()
{
    extern __shared__ __half attn_dyn[];
    __half* sm_q = attn_dyn;                         // [128][40]
    __half* sm_k = attn_dyn + 128 * 40;              // [kgrp][stage][128][40]
    __half* sm_v = sm_k + 2 * 2 * 128 * 40;          // [kgrp][stage][128][40]

    const int tid     = threadIdx.x;
    const int warp_id = tid / 32;
    const int ln      = tid % 32;
    const int blk_q   = blockIdx.x;
    const int blk_h   = blockIdx.y;
    const int blk_b   = blockIdx.z;
    const int qgrp    = warp_id & 7;
    const int kgrp    = warp_id >> 3;
    const int q_row0  = qgrp * 16;

    const __half* src_q = g_q + (size_t)(blk_b * SEQ + blk_q * 128) * DMODEL + blk_h * DH;

    {
        const int qr = tid >> 2;
        const int qc = (tid & 3) * 8;
        *(uint4*)&sm_q[qr * 40 + qc] = *(const uint4*)(src_q + (size_t)qr * DMODEL + qc);
    }

    const int prod_grp = tid >> 8;
    const int prod_row = (tid & 255) >> 2;
    const int prod_seg = tid & 3;
    const size_t base_kv = (size_t)blk_b * SEQ * DMODEL + (size_t)blk_h * DH;

    auto load_tiles = [&](int stage, int iter) {
        const int tile = prod_grp * 8 + iter;
        const int slot = (prod_grp * 2 + stage) * 128 * 40;
        #pragma unroll
        for (int half = 0; half < 2; half++) {
            const int r = prod_row + half * 64;
            const __half* kptr = g_k + base_kv + (size_t)(tile * 128 + r) * DMODEL;
            const __half* vptr = g_v + base_kv + (size_t)(tile * 128 + r) * DMODEL;
            cp_async16(smem_addr_u32(sm_k + slot + r * 40) + prod_seg * 16, kptr + prod_seg * 8);
            cp_async16(smem_addr_u32(sm_v + slot + r * 40) + prod_seg * 16, vptr + prod_seg * 8);
        }
    };

    load_tiles(0, 0); cp_async_commit();
    load_tiles(1, 1); cp_async_commit();
    __syncthreads();

    unsigned int frag_q[2][4];
    {
        const int qrow = q_row0 + (ln & 15);
        const int qcol = ((ln >> 4) & 1) * 8;
        #pragma unroll
        for (int ks = 0; ks < 2; ks++) {
            ldmatrix_x4(frag_q[ks][0], frag_q[ks][1], frag_q[ks][2], frag_q[ks][3],
                        smem_addr_u32(&sm_q[qrow * 40 + ks * 16 + qcol]));
        }
    }

    const int ln_lo7 = ln & 7;
    const int ln_c4  = ln >> 3;

    float acc_o[4][4] = {};
    float row_sum_a = 0.0f, row_sum_b = 0.0f;

    for (int iter = 0; iter < 8; iter++) {
        const int stage = iter & 1;
        cp_async_wait_one();
        __syncthreads();

        const int my_slot = (kgrp * 2 + stage) * 128 * 40;
        const unsigned int k_base = smem_addr_u32(sm_k + my_slot);
        const unsigned int v_base = smem_addr_u32(sm_v + my_slot);

        #pragma unroll
        for (int kc = 0; kc < 8; kc++) {
            unsigned int pfrag[4];
            #pragma unroll
            for (int sub = 0; sub < 2; sub++) {
                const int grp = kc * 2 + sub;
                float sc0 = 0.f, sc1 = 0.f, sc2 = 0.f, sc3 = 0.f;
                unsigned int kb0, kb1, kb2, kb3;
                ldmatrix_x4(kb0, kb1, kb2, kb3,
                            k_base + (unsigned int)(((grp * 8 + ln_lo7) * 40 + ln_c4 * 8) * 2));
                mma_f16_16816(sc0, sc1, sc2, sc3,
                              frag_q[0][0], frag_q[0][1], frag_q[0][2], frag_q[0][3], kb0, kb1);
                mma_f16_16816(sc0, sc1, sc2, sc3,
                              frag_q[1][0], frag_q[1][1], frag_q[1][2], frag_q[1][3], kb2, kb3);
                const unsigned int pe01 = exp2_f16x2(pack_f16x2(sc0, sc1));
                const unsigned int pe23 = exp2_f16x2(pack_f16x2(sc2, sc3));
                float fe0, fe1, fe2, fe3;
                unpack_f16x2(fe0, fe1, pe01);
                unpack_f16x2(fe2, fe3, pe23);
                row_sum_a += fe0 + fe1;
                row_sum_b += fe2 + fe3;
                pfrag[sub * 2]     = pe01;
                pfrag[sub * 2 + 1] = pe23;
            }
            #pragma unroll
            for (int np = 0; np < 2; np++) {
                unsigned int vb0, vb1, vb2, vb3;
                ldmatrix_x4_trans(vb0, vb1, vb2, vb3,
                                  v_base + (unsigned int)(((kc * 16 + (ln & 15)) * 40 + (np * 2 + (ln >> 4)) * 8) * 2));
                mma_f16_16816(acc_o[np*2][0], acc_o[np*2][1], acc_o[np*2][2], acc_o[np*2][3],
                              pfrag[0], pfrag[1], pfrag[2], pfrag[3], vb0, vb1);
                mma_f16_16816(acc_o[np*2+1][0], acc_o[np*2+1][1], acc_o[np*2+1][2], acc_o[np*2+1][3],
                              pfrag[0], pfrag[1], pfrag[2], pfrag[3], vb2, vb3);
            }
        }

        __syncthreads();
        if (iter + 2 < 8) load_tiles(stage, iter + 2);
        cp_async_commit();
    }

    row_sum_a += __shfl_xor_sync(0xffffffffu, row_sum_a, 1);
    row_sum_a += __shfl_xor_sync(0xffffffffu, row_sum_a, 2);
    row_sum_b += __shfl_xor_sync(0xffffffffu, row_sum_b, 1);
    row_sum_b += __shfl_xor_sync(0xffffffffu, row_sum_b, 2);

    float* mergeO = (float*)sm_k;            // [128][33] floats
    float* mergeL = (float*)sm_v;            // [128] floats
    const int out_row = ln >> 2;
    const int mrow_a  = qgrp * 16 + out_row;

    if (kgrp == 1) {
        #pragma unroll
        for (int nn = 0; nn < 4; nn++) {
            const int colx = nn * 8 + (ln & 3) * 2;
            mergeO[mrow_a * 33 + colx]           = acc_o[nn][0];
            mergeO[mrow_a * 33 + colx + 1]       = acc_o[nn][1];
            mergeO[(mrow_a + 8) * 33 + colx]     = acc_o[nn][2];
            mergeO[(mrow_a + 8) * 33 + colx + 1] = acc_o[nn][3];
        }
        if ((ln & 3) == 0) {
            mergeL[mrow_a]     = row_sum_a;
            mergeL[mrow_a + 8] = row_sum_b;
        }
    }
    __syncthreads();

    if (kgrp == 0) {
        row_sum_a += mergeL[mrow_a];
        row_sum_b += mergeL[mrow_a + 8];
        const float inv_a = 1.0f / row_sum_a;
        const float inv_b = 1.0f / row_sum_b;

        __half* out_ptr = g_aoh + (size_t)(blk_b * SEQ + blk_q * 128 + q_row0 + out_row) * DMODEL + blk_h * DH;
        #pragma unroll
        for (int nn = 0; nn < 4; nn++) {
            const int colx = nn * 8 + (ln & 3) * 2;
            const float oa0 = (acc_o[nn][0] + mergeO[mrow_a * 33 + colx])           * inv_a;
            const float oa1 = (acc_o[nn][1] + mergeO[mrow_a * 33 + colx + 1])       * inv_a;
            const float ob0 = (acc_o[nn][2] + mergeO[(mrow_a + 8) * 33 + colx])     * inv_b;
            const float ob1 = (acc_o[nn][3] + mergeO[(mrow_a + 8) * 33 + colx + 1]) * inv_b;
            *(__half2*)&out_ptr[colx]              = __floats2half2_rn(oa0, oa1);
            *(__half2*)&out_ptr[8 * DMODEL + colx] = __floats2half2_rn(ob0, ob1);
        }
    }
}

// ---------------------------------------------------------------------------
extern "C" void kernel_launch(void* const* d_in, const int* in_sizes, int n_in,
                              void* d_out, int out_size)
{
    const float* query = (const float*)d_in[0];
    const float* key   = (const float*)d_in[1];
    const float* value = (const float*)d_in[2];
    const float* Wq    = (const float*)d_in[3];
    const float* Wk    = (const float*)d_in[4];
    const float* Wv    = (const float*)d_in[5];
    const float* Wo    = (const float*)d_in[6];
    const float* bo    = (const float*)d_in[7];
    float* out = (float*)d_out;

    cudaFuncSetAttribute(attn_flash_splitk, cudaFuncAttributeMaxDynamicSharedMemorySize, ATTN_SMEM_BYTES);

    proj_gemm_f32in<<<dim3(4, 64, 3), 256>>>(query, key, value, Wq, Wk, Wv);
    attn_flash_splitk<<<dim3(16, NHEAD, BATCH), 512, ATTN_SMEM_BYTES>>>();
    out_proj_f32w<<<dim3(4, 64, 1), 256>>>(Wo, bo, out);
}